// round 16
// baseline (speedup 1.0000x reference)
#include <cuda_runtime.h>
#include <cuda_bf16.h>

// ---------------- problem constants ----------------
#define N0 6912      // 48*48*3
#define N1 27648     // 96*96*3
#define N2 110592    // 192*192*3
#define NTOT 145152
#define MAXB 100
#define CCAP 4096
#define S_TAIL 256u
#define HBINS 8192   // 13-bit conf histogram
#define GBLK 142     // 142*1024 >= NTOT
// K1: warp-autonomous 16-box tiles, per-warp cp.async double buffer
#define WTILE 16
#define NWT (NTOT / WTILE)     // 9072
#define K1NB 296               // 2 blocks/SM
#define K1T 256
#define WARPS 8
#define TF4 (WTILE * 85 / 4)   // 340 float4 per tile
#define K1SM (WARPS * 2 * TF4 * 16)   // 87040 bytes
// K4
#define K4T 256
#define K4SM 114688  // A(32KB) + SL(16KB) + sBox(64KB)

// ---------------- scratch (device globals; zero-initialized at load) ----------------
__device__ float    g_conf[NTOT];
__device__ unsigned g_keysA[NTOT];        // fallback-only scratch
__device__ unsigned g_hist13[HBINS];      // zeroed by k3 each launch
__device__ unsigned g_candK[CCAP], g_candV[CCAP];
__device__ float4   g_candBox[CCAP];
__device__ int      g_candCls[CCAP];
__device__ float4   g_bboxFB[NTOT];       // fallback-only scratch
__device__ float    g_partM[K1NB], g_partm[K1NB];
__device__ float    g_MM, g_mm;
__device__ int      g_posthr, g_negthr;
__device__ unsigned g_totalvalid;
__device__ unsigned g_ticket, g_overflow, g_done;

// ---------------- cp.async helpers ----------------
#define CP_ASYNC16(saddr, gptr) \
    asm volatile("cp.async.cg.shared.global [%0], [%1], 16;" \
                 :: "r"(saddr), "l"(gptr) : "memory")
#define CP_ASYNC_COMMIT()  asm volatile("cp.async.commit_group;" ::: "memory")
#define CP_ASYNC_WAIT0()   asm volatile("cp.async.wait_group 0;" ::: "memory")
#define CP_ASYNC_WAIT1()   asm volatile("cp.async.wait_group 1;" ::: "memory")

// order-preserving float<->uint encodings
__device__ __forceinline__ unsigned enc_ord(float f) {
    unsigned u = __float_as_uint(f);
    return (u & 0x80000000u) ? ~u : (u ^ 0x80000000u);
}
__device__ __forceinline__ float dec_ord(unsigned o) {
    unsigned u = (o & 0x80000000u) ? (o ^ 0x80000000u) : ~o;
    return __uint_as_float(u);
}

// Exact-equivalent IoU>0.5 test (guard band + exact division inside band).
__device__ __forceinline__ bool iou_gt_half(float4 a, float areaA, float4 b, float areaB) {
    float iw = fminf(a.z, b.z) - fmaxf(a.x, b.x); iw = fmaxf(iw, 0.0f);
    float ih = fminf(a.w, b.w) - fmaxf(a.y, b.y); ih = fmaxf(ih, 0.0f);
    float inter = iw * ih;
    float U = areaA + areaB - inter;
    float d = inter - 0.5f * U;
    if (fabsf(d) > 1e-4f * U) return d > 0.0f;
    return __fdiv_rn(inter, U) > 0.5f;
}

__device__ __forceinline__ const float* box_ptr(int gw,
        const float* g0, const float* g1, const float* g2,
        int& H, int& abase, int& local) {
    if (gw < N0)      { H = 48;  abase = 12; local = gw;           return g0 + (size_t)local * 85; }
    if (gw < N0 + N1) { H = 96;  abase = 6;  local = gw - N0;      return g1 + (size_t)local * 85; }
    H = 192; abase = 0; local = gw - N0 - N1; return g2 + (size_t)local * 85;
}

__device__ __forceinline__ float4 geom(const float* p, int local, int H, int abase,
                                       const float* anch) {
    float x = p[0], y = p[1], wv = p[2], hv = p[3];
    int a = local % 3;
    int cell = local / 3;
    int cx = cell % H;   // W == H
    int cy = cell / H;
    float aw = anch[abase + a * 2 + 0];
    float ah = anch[abase + a * 2 + 1];
    float bw = expf(wv) * aw;
    float bh = expf(hv) * ah;
    float Hf = (float)H;
    float X = __fdiv_rn(x + (float)cx, Hf);
    float Y = __fdiv_rn(y + (float)cy, Hf);
    return make_float4(X - bw * 0.5f, Y - bh * 0.5f, X + bw * 0.5f, Y + bh * 0.5f);
}

// 16-box tile -> first float4 (tiles never straddle tensors: 432 / 1728 / 6912)
__device__ __forceinline__ const float4* tile_src16(int t,
        const float* g0, const float* g1, const float* g2) {
    if (t < 432)  return (const float4*)(g0 + (size_t)t * WTILE * 85);
    if (t < 2160) return (const float4*)(g1 + (size_t)(t - 432) * WTILE * 85);
    return (const float4*)(g2 + (size_t)(t - 2160) * WTILE * 85);
}

// ---------------- K1: warp-autonomous pipelined stream + last-block thresholds ----------------
__global__ void __launch_bounds__(K1T)
k1_kernel(const float* __restrict__ g0,
          const float* __restrict__ g1,
          const float* __restrict__ g2) {
    extern __shared__ float S[];
    __shared__ float aM[WARPS], am[WARPS];
    __shared__ float s_MMg, s_mmg;
    __shared__ unsigned s_part2[K1T];
    __shared__ int s_last, s_pos, s_neg;

    const int b = blockIdx.x;
    const int tid = threadIdx.x;
    const int lane = tid & 31;
    const int wid = tid >> 5;

    unsigned sbase = (unsigned)__cvta_generic_to_shared(S);
    unsigned wbase = sbase + wid * (2 * TF4) * 16;
    float* WS = S + wid * (2 * TF4 * 4);

    float runM = -3.4e38f, runm = 3.4e38f;
    const int stride = K1NB * WARPS;   // 2368
    const int t0 = b * WARPS + wid;

    // prologue (every warp has >=3 tiles since 2368 < 9072)
    {
        const float4* in = tile_src16(t0, g0, g1, g2);
        for (int i = lane; i < TF4; i += 32) CP_ASYNC16(wbase + i * 16, in + i);
        CP_ASYNC_COMMIT();
    }
    int parity = 0;
    for (int t = t0; t < NWT; t += stride) {
        int nxt = t + stride;
        if (nxt < NWT) {
            const float4* in = tile_src16(nxt, g0, g1, g2);
            unsigned dst = wbase + (parity ? 0 : TF4 * 16);
            for (int i = lane; i < TF4; i += 32) CP_ASYNC16(dst + i * 16, in + i);
            CP_ASYNC_COMMIT();
            CP_ASYNC_WAIT1();
        } else {
            CP_ASYNC_WAIT0();
        }
        __syncwarp();

        const float* B = WS + (parity ? TF4 * 4 : 0);
        int box = lane >> 1, half = lane & 1;
        const float* pb = B + box * 85;
        float mx = -3.4e38f;
        int base2 = 5 + half * 40;
        #pragma unroll 8
        for (int i = 0; i < 40; ++i) mx = fmaxf(mx, pb[base2 + i]);
        mx = fmaxf(mx, __shfl_xor_sync(0xffffffffu, mx, 1));
        if (half == 0) {
            float c = pb[4];
            g_conf[t * WTILE + box] = c;
            atomicAdd(&g_hist13[enc_ord(c) >> 19], 1u);
        }
        runM = fmaxf(runM, mx);
        runm = fminf(runm, mx);
        __syncwarp();   // compute done before next iteration overwrites this buffer
        parity ^= 1;
    }

    // warp + block reduce M/m
    #pragma unroll
    for (int off = 16; off; off >>= 1) {
        runM = fmaxf(runM, __shfl_xor_sync(0xffffffffu, runM, off));
        runm = fminf(runm, __shfl_xor_sync(0xffffffffu, runm, off));
    }
    if (lane == 0) { aM[wid] = runM; am[wid] = runm; }
    __syncthreads();
    if (tid == 0) {
        float M = aM[0], m = am[0];
        #pragma unroll
        for (int i = 1; i < WARPS; ++i) { M = fmaxf(M, aM[i]); m = fminf(m, am[i]); }
        g_partM[b] = M;
        g_partm[b] = m;
        __threadfence();
        unsigned v = atomicAdd(&g_done, 1u);
        s_last = (v == (unsigned)(K1NB - 1)) ? 1 : 0;
    }
    __syncthreads();
    if (!s_last) return;
    __threadfence();

    // ===== last block: global M/m + two-tail thresholds =====
    {
        float M = -3.4e38f, m = 3.4e38f;
        for (int i = tid; i < K1NB; i += K1T) {
            M = fmaxf(M, g_partM[i]);
            m = fminf(m, g_partm[i]);
        }
        #pragma unroll
        for (int off = 16; off; off >>= 1) {
            M = fmaxf(M, __shfl_xor_sync(0xffffffffu, M, off));
            m = fminf(m, __shfl_xor_sync(0xffffffffu, m, off));
        }
        if (lane == 0) { aM[wid] = M; am[wid] = m; }
        __syncthreads();
        if (tid == 0) {
            #pragma unroll
            for (int i = 1; i < WARPS; ++i) { M = fmaxf(M, aM[i]); m = fminf(m, am[i]); }
            s_MMg = M; s_mmg = m;
            g_MM = M; g_mm = m;
            s_pos = 0x7FFFFFFF; s_neg = -1;
        }
    }
    unsigned* sh = (unsigned*)S;   // reuse dynamic smem (32KB of 87KB)
    #pragma unroll
    for (int i = 0; i < HBINS / K1T; ++i)
        sh[tid + i * K1T] = g_hist13[tid + i * K1T];
    __syncthreads();
    unsigned part = 0;
    #pragma unroll
    for (int i = 0; i < 32; ++i) part += sh[tid * 32 + i];
    s_part2[tid] = part;
    __syncthreads();
    unsigned x = part;
    for (int off = 1; off < K1T; off <<= 1) {
        unsigned add = (tid >= off) ? s_part2[tid - off] : 0u;
        __syncthreads();
        x += add;
        s_part2[tid] = x;
        __syncthreads();
    }
    const unsigned TOT = s_part2[K1T - 1];
    const unsigned totalneg = s_part2[127];        // bins 0..4095 (c<0)
    const unsigned totalpos = TOT - totalneg;      // bins 4096..8191 (c>0)
    const float Mg = s_MMg, mg = s_mmg;

    if (mg < 0.0f && totalneg > 0) {
        unsigned Sn = S_TAIL < totalneg ? S_TAIL : totalneg;
        if (tid < 128) {
            unsigned prev = (tid == 0) ? 0u : s_part2[tid - 1];
            if (x >= Sn && prev < Sn) {
                unsigned run = prev;
                for (int i = 0; i < 32; ++i) {
                    run += sh[tid * 32 + i];
                    if (run >= Sn) { s_neg = tid * 32 + i; break; }
                }
            }
        }
    }
    if (Mg > 0.0f && totalpos > 0) {
        unsigned Sp = S_TAIL < totalpos ? S_TAIL : totalpos;
        if (tid >= 128) {
            unsigned above_end = TOT - x;
            unsigned above_start = TOT - s_part2[tid - 1];
            if (above_end < Sp && above_start >= Sp) {
                unsigned run = above_end;
                for (int i = 31; i >= 0; --i) {
                    run += sh[tid * 32 + i];
                    if (run >= Sp) { s_pos = tid * 32 + i; break; }
                }
            }
        }
    }
    __syncthreads();
    if (tid == 0) {
        g_posthr = s_pos;
        g_negthr = s_neg;
        unsigned tv = 0;
        if (Mg > 0.0f) tv += totalpos;
        if (mg < 0.0f) tv += totalneg;
        g_totalvalid = tv;
    }
}

// ---------------- K3: lean compact + warp-cooperative decode + hist clean ----------------
__global__ void __launch_bounds__(1024)
k3_kernel(const float* __restrict__ g0,
          const float* __restrict__ g1,
          const float* __restrict__ g2,
          const float* __restrict__ anch) {
    const int tid = threadIdx.x;
    const int lane = tid & 31;
    const float M = g_MM, m = g_mm;
    const int posthr = g_posthr, negthr = g_negthr;

    int i = blockIdx.x * 1024 + tid;
    if (i < HBINS) g_hist13[i] = 0u;   // clean for next launch

    bool inb = (i < NTOT);
    float c = inb ? g_conf[i] : 0.0f;
    int bin = (int)(enc_ord(c) >> 19);
    bool take = inb && (bin >= posthr || bin <= negthr);
    unsigned key = 0u;
    if (take) {
        float score = fmaxf(c * M, c * m);
        if (score > 0.0f) key = ~enc_ord(score);
        else take = false;
    }
    unsigned pos = 0;
    if (take) {
        pos = atomicAdd(&g_ticket, 1u);
        if (pos < CCAP) { g_candK[pos] = key; g_candV[pos] = (unsigned)i; }
        else            { g_overflow = 1u; take = false; }
    }
    unsigned tb = __ballot_sync(0xffffffffu, take);
    while (tb) {
        int src = __ffs(tb) - 1; tb &= tb - 1;
        int cgw = (int)__shfl_sync(0xffffffffu, (unsigned)i, src);
        unsigned cpos = __shfl_sync(0xffffffffu, pos, src);
        int H, abase, local;
        const float* p = box_ptr(cgw, g0, g1, g2, H, abase, local);
        float bvv = -3.4e38f;
        int bi = 0;
        for (int cc = lane; cc < 80; cc += 32) {
            float v = p[5 + cc];
            if (v > bvv) { bvv = v; bi = cc; }
        }
        #pragma unroll
        for (int off = 16; off; off >>= 1) {
            float ov = __shfl_xor_sync(0xffffffffu, bvv, off);
            int   oi = __shfl_xor_sync(0xffffffffu, bi, off);
            if (ov > bvv || (ov == bvv && oi < bi)) { bvv = ov; bi = oi; }
        }
        if (lane == 0) {
            g_candBox[cpos] = geom(p, local, H, abase, anch);
            g_candCls[cpos] = bi;
        }
    }
}

// ---------------- K4: 256-thread tail: bitonic sort + matrix NMS + output + self-clean ----------------
__global__ void __launch_bounds__(K4T, 1)
k4_kernel(const float* __restrict__ g0,
          const float* __restrict__ g1,
          const float* __restrict__ g2,
          const float* __restrict__ anch,
          float* __restrict__ out, int out_size) {
    extern __shared__ unsigned char DS[];
    unsigned long long* A = (unsigned long long*)DS;        // 32KB (4096 u64)
    unsigned* SL = (unsigned*)(DS + 32768);                 // 16KB
    float4*  sBox = (float4*)(DS + 49152);                  // 64KB

    __shared__ unsigned mat[K4T][8];
    __shared__ float s_areaC[K4T];
    __shared__ unsigned s_alive[8];
    __shared__ int s_opos[MAXB];
    __shared__ int s_fbidx[MAXB];
    __shared__ float4 selB[MAXB];
    __shared__ float  selA[MAXB];
    __shared__ float4 o_box[MAXB];
    __shared__ float  o_score[MAXB];
    __shared__ int    o_cls[MAXB];
    __shared__ int s_nsel;

    const int tid = threadIdx.x;
    const int lane = tid & 31;
    const int wid = tid >> 5;

    unsigned totalvalid = g_totalvalid;
    int C = (int)(g_ticket < (unsigned)CCAP ? g_ticket : (unsigned)CCAP);
    int ovf = (int)g_overflow;
    if (tid == 0) s_nsel = 0;
    __syncthreads();

    if (C > 0) {
        int NP = 128;
        while (NP < C) NP <<= 1;

        for (int i = tid; i < NP; i += K4T) {
            if (i < C) { A[i] = ((unsigned long long)g_candK[i] << 32) | g_candV[i]; SL[i] = (unsigned)i; }
            else       { A[i] = ~0ull; SL[i] = 0u; }
        }
        __syncthreads();

        for (int k = 2; k <= NP; k <<= 1) {
            for (int j = k >> 1; j > 0; j >>= 1) {
                for (int i = tid; i < NP; i += K4T) {
                    int ixj = i ^ j;
                    if (ixj > i) {
                        bool up = ((i & k) == 0);
                        unsigned long long a = A[i], bb = A[ixj];
                        if ((up && a > bb) || (!up && a < bb)) {
                            A[i] = bb; A[ixj] = a;
                            unsigned t = SL[i]; SL[i] = SL[ixj]; SL[ixj] = t;
                        }
                    }
                }
                __syncthreads();
            }
        }

        for (int i = tid; i < C; i += K4T) sBox[i] = g_candBox[SL[i]];
        __syncthreads();

        for (int base = 0; base < C; base += K4T) {
            int t = base + tid;
            int lim = (C - base) < K4T ? (C - base) : K4T;
            bool alive = (tid < lim);
            float4 bx = make_float4(0.f, 0.f, 0.f, 0.f);
            float ar = 0.f;
            if (alive) {
                bx = sBox[t];
                ar = (bx.z - bx.x) * (bx.w - bx.y);
            }
            s_areaC[tid] = ar;
            if (alive) {
                int n0 = s_nsel;
                for (int s = 0; s < n0; ++s) {
                    if (iou_gt_half(bx, ar, selB[s], selA[s])) { alive = false; break; }
                }
            }
            __syncthreads();

            unsigned row[8] = {0u,0u,0u,0u,0u,0u,0u,0u};
            if (alive) {
                for (int j = tid + 1; j < lim; ++j) {
                    float4 ob = sBox[base + j];
                    if (iou_gt_half(bx, ar, ob, s_areaC[j])) row[j >> 5] |= 1u << (j & 31);
                }
            }
            #pragma unroll
            for (int q = 0; q < 8; ++q) mat[tid][q] = row[q];

            unsigned bal = __ballot_sync(0xffffffffu, alive);
            if (lane == 0) s_alive[wid] = bal;
            __syncthreads();

            if (wid == 0) {
                int nsel = s_nsel;
                unsigned aw = (lane < 8) ? s_alive[lane] : 0u;
                while (nsel < MAXB) {
                    unsigned nz = __ballot_sync(0xffffffffu, aw != 0u);
                    if (!nz) break;
                    int fw = __ffs(nz) - 1;
                    unsigned w = __shfl_sync(0xffffffffu, aw, fw);
                    int fb = __ffs(w) - 1;
                    int f = (fw << 5) + fb;
                    if (lane < 8) {
                        aw &= ~mat[f][lane];
                        if (lane == fw) aw &= ~(1u << fb);
                    }
                    if (lane == 0) {
                        int gp = base + f;
                        s_opos[nsel] = gp;
                        float4 sbx = sBox[gp];
                        selB[nsel] = sbx;
                        selA[nsel] = (sbx.z - sbx.x) * (sbx.w - sbx.y);
                    }
                    nsel++;
                }
                if (lane == 0) s_nsel = nsel;
            }
            __syncthreads();
            if (s_nsel >= MAXB) break;
        }

        int ns = s_nsel;
        for (int j = tid; j < ns; j += K4T) {
            int i = s_opos[j];
            o_box[j]   = sBox[i];
            o_score[j] = dec_ord(~(unsigned)(A[i] >> 32));
            o_cls[j]   = g_candCls[SL[i]];
        }
        __syncthreads();
    }

    // ================= fallback (exactness guard; normally never taken) =================
    {
        bool need_fb = (s_nsel < MAXB) && (ovf || totalvalid > (unsigned)C);
        if (need_fb) {
            float M = g_MM, m = g_mm;
            for (int gw = tid; gw < NTOT; gw += K4T) {
                float c = g_conf[gw];
                float score = fmaxf(c * M, c * m);
                g_keysA[gw] = (score > 0.0f) ? ~enc_ord(score) : 0xFFFFFFFFu;
                int H, abase, local;
                const float* p = box_ptr(gw, g0, g1, g2, H, abase, local);
                g_bboxFB[gw] = geom(p, local, H, abase, anch);
            }
            if (tid == 0) s_nsel = 0;
            __syncthreads();
            unsigned long long* red = A;
            for (int r = 0; r < MAXB; ++r) {
                unsigned long long best = ~0ull;
                for (int i = tid; i < NTOT; i += K4T) {
                    unsigned k = g_keysA[i];
                    if (k < 0x80000000u) {
                        unsigned long long cmp = ((unsigned long long)k << 32) | (unsigned)i;
                        if (cmp < best) best = cmp;
                    }
                }
                red[tid] = best;
                __syncthreads();
                for (int off = K4T / 2; off; off >>= 1) {
                    if (tid < off && red[tid + off] < red[tid]) red[tid] = red[tid + off];
                    __syncthreads();
                }
                best = red[0];
                __syncthreads();
                if (best == ~0ull) break;
                unsigned j = (unsigned)(best & 0xFFFFFFFFu);
                float4 bj = g_bboxFB[j];
                float aj = (bj.z - bj.x) * (bj.w - bj.y);
                if (tid == 0) {
                    int n = s_nsel;
                    o_box[n]   = bj;
                    o_score[n] = dec_ord(~(unsigned)(best >> 32));
                    s_fbidx[n] = (int)j;
                    s_nsel = n + 1;
                }
                for (int i = tid; i < NTOT; i += K4T) {
                    unsigned k = g_keysA[i];
                    if (k < 0x80000000u) {
                        float4 bi = g_bboxFB[i];
                        float ai = (bi.z - bi.x) * (bi.w - bi.y);
                        if (iou_gt_half(bi, ai, bj, aj)) g_keysA[i] = 0xFFFFFFFFu;
                    }
                }
                __syncthreads();
            }
            for (int j2 = tid; j2 < s_nsel; j2 += K4T) {
                int gw = s_fbidx[j2];
                int H, abase, local;
                const float* p = box_ptr(gw, g0, g1, g2, H, abase, local);
                float bestv = -3.4e38f; int bi = 0;
                for (int cc = 0; cc < 80; ++cc) {
                    float v = p[5 + cc];
                    if (v > bestv) { bestv = v; bi = cc; }
                }
                o_cls[j2] = bi;
            }
            __syncthreads();
        }
    }

    // ================= output =================
    int ns = s_nsel;
    for (int i = tid; i < out_size; i += K4T) {
        float v = 0.0f;
        if (i < 400) {
            int j = i >> 2;
            if (j < ns) v = ((float*)o_box)[i];
        } else if (i < 500) {
            int j = i - 400;
            if (j < ns) v = o_score[j];
        } else if (i < 600) {
            int j = i - 500;
            if (j < ns) v = (float)o_cls[j];
        } else if (i == 600) {
            v = (float)ns;
        }
        out[i] = v;
    }

    // ---- self-clean persistent state for next launch ----
    __syncthreads();
    if (tid == 0) {
        g_ticket = 0u;
        g_overflow = 0u;
        g_done = 0u;
    }
}

// ---------------- launch ----------------
extern "C" void kernel_launch(void* const* d_in, const int* in_sizes, int n_in,
                              void* d_out, int out_size) {
    const float* g0   = (const float*)d_in[0];
    const float* g1   = (const float*)d_in[1];
    const float* g2   = (const float*)d_in[2];
    const float* anch = (const float*)d_in[3];
    float* out = (float*)d_out;

    cudaFuncSetAttribute(k1_kernel, cudaFuncAttributeMaxDynamicSharedMemorySize, K1SM);
    cudaFuncSetAttribute(k4_kernel, cudaFuncAttributeMaxDynamicSharedMemorySize, K4SM);

    k1_kernel<<<K1NB, K1T, K1SM>>>(g0, g1, g2);
    k3_kernel<<<GBLK, 1024>>>(g0, g1, g2, anch);
    k4_kernel<<<1, K4T, K4SM>>>(g0, g1, g2, anch, out, out_size);
}

// round 17
// speedup vs baseline: 1.0073x; 1.0073x over previous
#include <cuda_runtime.h>
#include <cuda_bf16.h>

// ---------------- problem constants ----------------
#define N0 6912      // 48*48*3
#define N1 27648     // 96*96*3
#define N2 110592    // 192*192*3
#define NTOT 145152
#define MAXB 100
#define CCAP 4096
#define S_TAIL 256u
#define HBINS 8192   // 13-bit conf histogram
#define GBLK 142     // 142*1024 >= NTOT
// K1: 128-box tiles staged by 1D bulk-TMA, double buffered
#define BPB 128
#define NTILES 1134            // NTOT/128
#define K1NB 296               // 2 blocks/SM
#define K1T 256
#define TILE_F (BPB * 85)      // 10880 floats
#define TBYTES (TILE_F * 4)    // 43520 bytes (mult of 16)
#define K1SM (2 * TBYTES)      // 87040
// K4
#define K4T 256
#define K4SM 114688  // A(32KB) + SL(16KB) + sBox(64KB)

// ---------------- scratch (device globals; zero-initialized at load) ----------------
__device__ float    g_conf[NTOT];
__device__ unsigned g_keysA[NTOT];        // fallback-only scratch
__device__ unsigned g_hist13[HBINS];      // zeroed by k3 each launch
__device__ unsigned g_candK[CCAP], g_candV[CCAP];
__device__ float4   g_candBox[CCAP];
__device__ int      g_candCls[CCAP];
__device__ float4   g_bboxFB[NTOT];       // fallback-only scratch
__device__ float    g_partM[K1NB], g_partm[K1NB];
__device__ float    g_MM, g_mm;
__device__ int      g_posthr, g_negthr;
__device__ unsigned g_totalvalid;
__device__ unsigned g_ticket, g_overflow, g_done;

// ---------------- mbarrier / bulk-TMA helpers ----------------
#define MBAR_INIT(addr, cnt) \
    asm volatile("mbarrier.init.shared.b64 [%0], %1;" :: "r"(addr), "r"(cnt) : "memory")
#define MBAR_EXPECT_TX(addr, bytes) \
    asm volatile("mbarrier.arrive.expect_tx.shared.b64 _, [%0], %1;" \
                 :: "r"(addr), "r"(bytes) : "memory")
#define BULK_G2S(dst, src, bytes, mbar) \
    asm volatile("cp.async.bulk.shared::cta.global.mbarrier::complete_tx::bytes " \
                 "[%0], [%1], %2, [%3];" \
                 :: "r"(dst), "l"(src), "r"(bytes), "r"(mbar) : "memory")
__device__ __forceinline__ void mbar_wait(unsigned addr, int parity) {
    unsigned done;
    asm volatile(
        "{\n\t.reg .pred p;\n\t"
        "mbarrier.try_wait.parity.acquire.cta.shared::cta.b64 p, [%1], %2;\n\t"
        "selp.b32 %0, 1, 0, p;\n\t}"
        : "=r"(done) : "r"(addr), "r"((unsigned)parity) : "memory");
    if (!done) {
        asm volatile(
            "{\n\t.reg .pred P1;\n\t"
            "WL_%=:\n\t"
            "mbarrier.try_wait.parity.acquire.cta.shared::cta.b64 P1, [%0], %1, 0x989680;\n\t"
            "@P1 bra.uni WD_%=;\n\t"
            "bra.uni WL_%=;\n\t"
            "WD_%=:\n\t}"
            :: "r"(addr), "r"((unsigned)parity) : "memory");
    }
}

// order-preserving float<->uint encodings
__device__ __forceinline__ unsigned enc_ord(float f) {
    unsigned u = __float_as_uint(f);
    return (u & 0x80000000u) ? ~u : (u ^ 0x80000000u);
}
__device__ __forceinline__ float dec_ord(unsigned o) {
    unsigned u = (o & 0x80000000u) ? (o ^ 0x80000000u) : ~o;
    return __uint_as_float(u);
}

// Exact-equivalent IoU>0.5 test (guard band + exact division inside band).
__device__ __forceinline__ bool iou_gt_half(float4 a, float areaA, float4 b, float areaB) {
    float iw = fminf(a.z, b.z) - fmaxf(a.x, b.x); iw = fmaxf(iw, 0.0f);
    float ih = fminf(a.w, b.w) - fmaxf(a.y, b.y); ih = fmaxf(ih, 0.0f);
    float inter = iw * ih;
    float U = areaA + areaB - inter;
    float d = inter - 0.5f * U;
    if (fabsf(d) > 1e-4f * U) return d > 0.0f;
    return __fdiv_rn(inter, U) > 0.5f;
}

__device__ __forceinline__ const float* box_ptr(int gw,
        const float* g0, const float* g1, const float* g2,
        int& H, int& abase, int& local) {
    if (gw < N0)      { H = 48;  abase = 12; local = gw;           return g0 + (size_t)local * 85; }
    if (gw < N0 + N1) { H = 96;  abase = 6;  local = gw - N0;      return g1 + (size_t)local * 85; }
    H = 192; abase = 0; local = gw - N0 - N1; return g2 + (size_t)local * 85;
}

__device__ __forceinline__ float4 geom(const float* p, int local, int H, int abase,
                                       const float* anch) {
    float x = p[0], y = p[1], wv = p[2], hv = p[3];
    int a = local % 3;
    int cell = local / 3;
    int cx = cell % H;   // W == H
    int cy = cell / H;
    float aw = anch[abase + a * 2 + 0];
    float ah = anch[abase + a * 2 + 1];
    float bw = expf(wv) * aw;
    float bh = expf(hv) * ah;
    float Hf = (float)H;
    float X = __fdiv_rn(x + (float)cx, Hf);
    float Y = __fdiv_rn(y + (float)cy, Hf);
    return make_float4(X - bw * 0.5f, Y - bh * 0.5f, X + bw * 0.5f, Y + bh * 0.5f);
}

// 128-box tile -> global source (tiles never straddle tensors: 54 / 216 / 864)
__device__ __forceinline__ const float* tile_src(int t,
        const float* g0, const float* g1, const float* g2) {
    if (t < 54)  return g0 + (size_t)t * TILE_F;
    if (t < 270) return g1 + (size_t)(t - 54) * TILE_F;
    return g2 + (size_t)(t - 270) * TILE_F;
}

// ---------------- K1: bulk-TMA double-buffered stream + last-block thresholds ----------------
__global__ void __launch_bounds__(K1T)
k1_kernel(const float* __restrict__ g0,
          const float* __restrict__ g1,
          const float* __restrict__ g2) {
    extern __shared__ float S[];
    __shared__ __align__(8) unsigned long long mbar[2];
    __shared__ float aM[8], am[8];
    __shared__ float s_MMg, s_mmg;
    __shared__ unsigned s_part2[K1T];
    __shared__ int s_last, s_pos, s_neg;

    const int b = blockIdx.x;
    const int tid = threadIdx.x;
    const int lane = tid & 31;
    const int wid = tid >> 5;

    unsigned sbase = (unsigned)__cvta_generic_to_shared(S);
    unsigned mb = (unsigned)__cvta_generic_to_shared(mbar);

    if (tid == 0) { MBAR_INIT(mb, 1); MBAR_INIT(mb + 8, 1); }
    __syncthreads();

    float runM = -3.4e38f, runm = 3.4e38f;

    // prologue: issue first tile into buffer 0
    if (tid == 0) {
        MBAR_EXPECT_TX(mb, TBYTES);
        BULK_G2S(sbase, tile_src(b, g0, g1, g2), TBYTES, mb);
    }

    int parity = 0;
    int phase[2] = {0, 0};
    for (int tile = b; tile < NTILES; tile += K1NB) {
        int nxt = tile + K1NB;
        if (nxt < NTILES && tid == 0) {
            unsigned mbn = mb + (1 - parity) * 8;
            MBAR_EXPECT_TX(mbn, TBYTES);
            BULK_G2S(sbase + (1 - parity) * TBYTES, tile_src(nxt, g0, g1, g2), TBYTES, mbn);
        }
        mbar_wait(mb + parity * 8, phase[parity]);
        phase[parity] ^= 1;

        const float* B = S + parity * TILE_F;
        int box = tid >> 1, half = tid & 1;
        const float* pb = B + box * 85;
        float mx = -3.4e38f;
        int base2 = 5 + half * 40;
        #pragma unroll 8
        for (int i = 0; i < 40; ++i) mx = fmaxf(mx, pb[base2 + i]);
        mx = fmaxf(mx, __shfl_xor_sync(0xffffffffu, mx, 1));
        if (half == 0) {
            float c = pb[4];
            g_conf[tile * BPB + box] = c;
            atomicAdd(&g_hist13[enc_ord(c) >> 19], 1u);
        }
        runM = fmaxf(runM, mx);
        runm = fminf(runm, mx);

        __syncthreads();   // all compute done before this buffer is re-issued
        parity ^= 1;
    }

    // block reduce M/m, publish partial, done-counter
    #pragma unroll
    for (int off = 16; off; off >>= 1) {
        runM = fmaxf(runM, __shfl_xor_sync(0xffffffffu, runM, off));
        runm = fminf(runm, __shfl_xor_sync(0xffffffffu, runm, off));
    }
    if (lane == 0) { aM[wid] = runM; am[wid] = runm; }
    __syncthreads();
    if (tid == 0) {
        float M = aM[0], m = am[0];
        #pragma unroll
        for (int i = 1; i < 8; ++i) { M = fmaxf(M, aM[i]); m = fminf(m, am[i]); }
        g_partM[b] = M;
        g_partm[b] = m;
        __threadfence();
        unsigned v = atomicAdd(&g_done, 1u);
        s_last = (v == (unsigned)(K1NB - 1)) ? 1 : 0;
    }
    __syncthreads();
    if (!s_last) return;
    __threadfence();

    // ===== last block: global M/m + two-tail thresholds =====
    {
        float M = -3.4e38f, m = 3.4e38f;
        for (int i = tid; i < K1NB; i += K1T) {
            M = fmaxf(M, g_partM[i]);
            m = fminf(m, g_partm[i]);
        }
        #pragma unroll
        for (int off = 16; off; off >>= 1) {
            M = fmaxf(M, __shfl_xor_sync(0xffffffffu, M, off));
            m = fminf(m, __shfl_xor_sync(0xffffffffu, m, off));
        }
        if (lane == 0) { aM[wid] = M; am[wid] = m; }
        __syncthreads();
        if (tid == 0) {
            #pragma unroll
            for (int i = 1; i < 8; ++i) { M = fmaxf(M, aM[i]); m = fminf(m, am[i]); }
            s_MMg = M; s_mmg = m;
            g_MM = M; g_mm = m;
            s_pos = 0x7FFFFFFF; s_neg = -1;
        }
    }
    unsigned* sh = (unsigned*)S;   // reuse dynamic smem (32KB of 87KB)
    #pragma unroll
    for (int i = 0; i < HBINS / K1T; ++i)
        sh[tid + i * K1T] = g_hist13[tid + i * K1T];
    __syncthreads();
    unsigned part = 0;
    #pragma unroll
    for (int i = 0; i < 32; ++i) part += sh[tid * 32 + i];
    s_part2[tid] = part;
    __syncthreads();
    unsigned x = part;
    for (int off = 1; off < K1T; off <<= 1) {
        unsigned add = (tid >= off) ? s_part2[tid - off] : 0u;
        __syncthreads();
        x += add;
        s_part2[tid] = x;
        __syncthreads();
    }
    const unsigned TOT = s_part2[K1T - 1];
    const unsigned totalneg = s_part2[127];        // bins 0..4095 (c<0)
    const unsigned totalpos = TOT - totalneg;      // bins 4096..8191 (c>0)
    const float Mg = s_MMg, mg = s_mmg;

    if (mg < 0.0f && totalneg > 0) {
        unsigned Sn = S_TAIL < totalneg ? S_TAIL : totalneg;
        if (tid < 128) {
            unsigned prev = (tid == 0) ? 0u : s_part2[tid - 1];
            if (x >= Sn && prev < Sn) {
                unsigned run = prev;
                for (int i = 0; i < 32; ++i) {
                    run += sh[tid * 32 + i];
                    if (run >= Sn) { s_neg = tid * 32 + i; break; }
                }
            }
        }
    }
    if (Mg > 0.0f && totalpos > 0) {
        unsigned Sp = S_TAIL < totalpos ? S_TAIL : totalpos;
        if (tid >= 128) {
            unsigned above_end = TOT - x;
            unsigned above_start = TOT - s_part2[tid - 1];
            if (above_end < Sp && above_start >= Sp) {
                unsigned run = above_end;
                for (int i = 31; i >= 0; --i) {
                    run += sh[tid * 32 + i];
                    if (run >= Sp) { s_pos = tid * 32 + i; break; }
                }
            }
        }
    }
    __syncthreads();
    if (tid == 0) {
        g_posthr = s_pos;
        g_negthr = s_neg;
        unsigned tv = 0;
        if (Mg > 0.0f) tv += totalpos;
        if (mg < 0.0f) tv += totalneg;
        g_totalvalid = tv;
    }
}

// ---------------- K3: lean compact + warp-cooperative decode + hist clean ----------------
__global__ void __launch_bounds__(1024)
k3_kernel(const float* __restrict__ g0,
          const float* __restrict__ g1,
          const float* __restrict__ g2,
          const float* __restrict__ anch) {
    const int tid = threadIdx.x;
    const int lane = tid & 31;
    const float M = g_MM, m = g_mm;
    const int posthr = g_posthr, negthr = g_negthr;

    int i = blockIdx.x * 1024 + tid;
    if (i < HBINS) g_hist13[i] = 0u;   // clean for next launch

    bool inb = (i < NTOT);
    float c = inb ? g_conf[i] : 0.0f;
    int bin = (int)(enc_ord(c) >> 19);
    bool take = inb && (bin >= posthr || bin <= negthr);
    unsigned key = 0u;
    if (take) {
        float score = fmaxf(c * M, c * m);
        if (score > 0.0f) key = ~enc_ord(score);
        else take = false;
    }
    unsigned pos = 0;
    if (take) {
        pos = atomicAdd(&g_ticket, 1u);
        if (pos < CCAP) { g_candK[pos] = key; g_candV[pos] = (unsigned)i; }
        else            { g_overflow = 1u; take = false; }
    }
    unsigned tb = __ballot_sync(0xffffffffu, take);
    while (tb) {
        int src = __ffs(tb) - 1; tb &= tb - 1;
        int cgw = (int)__shfl_sync(0xffffffffu, (unsigned)i, src);
        unsigned cpos = __shfl_sync(0xffffffffu, pos, src);
        int H, abase, local;
        const float* p = box_ptr(cgw, g0, g1, g2, H, abase, local);
        float bvv = -3.4e38f;
        int bi = 0;
        for (int cc = lane; cc < 80; cc += 32) {
            float v = p[5 + cc];
            if (v > bvv) { bvv = v; bi = cc; }
        }
        #pragma unroll
        for (int off = 16; off; off >>= 1) {
            float ov = __shfl_xor_sync(0xffffffffu, bvv, off);
            int   oi = __shfl_xor_sync(0xffffffffu, bi, off);
            if (ov > bvv || (ov == bvv && oi < bi)) { bvv = ov; bi = oi; }
        }
        if (lane == 0) {
            g_candBox[cpos] = geom(p, local, H, abase, anch);
            g_candCls[cpos] = bi;
        }
    }
}

// ---------------- K4: 256-thread tail: bitonic sort + matrix NMS + output + self-clean ----------------
__global__ void __launch_bounds__(K4T, 1)
k4_kernel(const float* __restrict__ g0,
          const float* __restrict__ g1,
          const float* __restrict__ g2,
          const float* __restrict__ anch,
          float* __restrict__ out, int out_size) {
    extern __shared__ unsigned char DS[];
    unsigned long long* A = (unsigned long long*)DS;        // 32KB (4096 u64)
    unsigned* SL = (unsigned*)(DS + 32768);                 // 16KB
    float4*  sBox = (float4*)(DS + 49152);                  // 64KB

    __shared__ unsigned mat[K4T][8];
    __shared__ float s_areaC[K4T];
    __shared__ unsigned s_alive[8];
    __shared__ int s_opos[MAXB];
    __shared__ int s_fbidx[MAXB];
    __shared__ float4 selB[MAXB];
    __shared__ float  selA[MAXB];
    __shared__ float4 o_box[MAXB];
    __shared__ float  o_score[MAXB];
    __shared__ int    o_cls[MAXB];
    __shared__ int s_nsel;

    const int tid = threadIdx.x;
    const int lane = tid & 31;
    const int wid = tid >> 5;

    unsigned totalvalid = g_totalvalid;
    int C = (int)(g_ticket < (unsigned)CCAP ? g_ticket : (unsigned)CCAP);
    int ovf = (int)g_overflow;
    if (tid == 0) s_nsel = 0;
    __syncthreads();

    if (C > 0) {
        int NP = 128;
        while (NP < C) NP <<= 1;

        for (int i = tid; i < NP; i += K4T) {
            if (i < C) { A[i] = ((unsigned long long)g_candK[i] << 32) | g_candV[i]; SL[i] = (unsigned)i; }
            else       { A[i] = ~0ull; SL[i] = 0u; }
        }
        __syncthreads();

        for (int k = 2; k <= NP; k <<= 1) {
            for (int j = k >> 1; j > 0; j >>= 1) {
                for (int i = tid; i < NP; i += K4T) {
                    int ixj = i ^ j;
                    if (ixj > i) {
                        bool up = ((i & k) == 0);
                        unsigned long long a = A[i], bb = A[ixj];
                        if ((up && a > bb) || (!up && a < bb)) {
                            A[i] = bb; A[ixj] = a;
                            unsigned t = SL[i]; SL[i] = SL[ixj]; SL[ixj] = t;
                        }
                    }
                }
                __syncthreads();
            }
        }

        for (int i = tid; i < C; i += K4T) sBox[i] = g_candBox[SL[i]];
        __syncthreads();

        for (int base = 0; base < C; base += K4T) {
            int t = base + tid;
            int lim = (C - base) < K4T ? (C - base) : K4T;
            bool alive = (tid < lim);
            float4 bx = make_float4(0.f, 0.f, 0.f, 0.f);
            float ar = 0.f;
            if (alive) {
                bx = sBox[t];
                ar = (bx.z - bx.x) * (bx.w - bx.y);
            }
            s_areaC[tid] = ar;
            if (alive) {
                int n0 = s_nsel;
                for (int s = 0; s < n0; ++s) {
                    if (iou_gt_half(bx, ar, selB[s], selA[s])) { alive = false; break; }
                }
            }
            __syncthreads();

            unsigned row[8] = {0u,0u,0u,0u,0u,0u,0u,0u};
            if (alive) {
                for (int j = tid + 1; j < lim; ++j) {
                    float4 ob = sBox[base + j];
                    if (iou_gt_half(bx, ar, ob, s_areaC[j])) row[j >> 5] |= 1u << (j & 31);
                }
            }
            #pragma unroll
            for (int q = 0; q < 8; ++q) mat[tid][q] = row[q];

            unsigned bal = __ballot_sync(0xffffffffu, alive);
            if (lane == 0) s_alive[wid] = bal;
            __syncthreads();

            if (wid == 0) {
                int nsel = s_nsel;
                unsigned aw = (lane < 8) ? s_alive[lane] : 0u;
                while (nsel < MAXB) {
                    unsigned nz = __ballot_sync(0xffffffffu, aw != 0u);
                    if (!nz) break;
                    int fw = __ffs(nz) - 1;
                    unsigned w = __shfl_sync(0xffffffffu, aw, fw);
                    int fb = __ffs(w) - 1;
                    int f = (fw << 5) + fb;
                    if (lane < 8) {
                        aw &= ~mat[f][lane];
                        if (lane == fw) aw &= ~(1u << fb);
                    }
                    if (lane == 0) {
                        int gp = base + f;
                        s_opos[nsel] = gp;
                        float4 sbx = sBox[gp];
                        selB[nsel] = sbx;
                        selA[nsel] = (sbx.z - sbx.x) * (sbx.w - sbx.y);
                    }
                    nsel++;
                }
                if (lane == 0) s_nsel = nsel;
            }
            __syncthreads();
            if (s_nsel >= MAXB) break;
        }

        int ns = s_nsel;
        for (int j = tid; j < ns; j += K4T) {
            int i = s_opos[j];
            o_box[j]   = sBox[i];
            o_score[j] = dec_ord(~(unsigned)(A[i] >> 32));
            o_cls[j]   = g_candCls[SL[i]];
        }
        __syncthreads();
    }

    // ================= fallback (exactness guard; normally never taken) =================
    {
        bool need_fb = (s_nsel < MAXB) && (ovf || totalvalid > (unsigned)C);
        if (need_fb) {
            float M = g_MM, m = g_mm;
            for (int gw = tid; gw < NTOT; gw += K4T) {
                float c = g_conf[gw];
                float score = fmaxf(c * M, c * m);
                g_keysA[gw] = (score > 0.0f) ? ~enc_ord(score) : 0xFFFFFFFFu;
                int H, abase, local;
                const float* p = box_ptr(gw, g0, g1, g2, H, abase, local);
                g_bboxFB[gw] = geom(p, local, H, abase, anch);
            }
            if (tid == 0) s_nsel = 0;
            __syncthreads();
            unsigned long long* red = A;
            for (int r = 0; r < MAXB; ++r) {
                unsigned long long best = ~0ull;
                for (int i = tid; i < NTOT; i += K4T) {
                    unsigned k = g_keysA[i];
                    if (k < 0x80000000u) {
                        unsigned long long cmp = ((unsigned long long)k << 32) | (unsigned)i;
                        if (cmp < best) best = cmp;
                    }
                }
                red[tid] = best;
                __syncthreads();
                for (int off = K4T / 2; off; off >>= 1) {
                    if (tid < off && red[tid + off] < red[tid]) red[tid] = red[tid + off];
                    __syncthreads();
                }
                best = red[0];
                __syncthreads();
                if (best == ~0ull) break;
                unsigned j = (unsigned)(best & 0xFFFFFFFFu);
                float4 bj = g_bboxFB[j];
                float aj = (bj.z - bj.x) * (bj.w - bj.y);
                if (tid == 0) {
                    int n = s_nsel;
                    o_box[n]   = bj;
                    o_score[n] = dec_ord(~(unsigned)(best >> 32));
                    s_fbidx[n] = (int)j;
                    s_nsel = n + 1;
                }
                for (int i = tid; i < NTOT; i += K4T) {
                    unsigned k = g_keysA[i];
                    if (k < 0x80000000u) {
                        float4 bi = g_bboxFB[i];
                        float ai = (bi.z - bi.x) * (bi.w - bi.y);
                        if (iou_gt_half(bi, ai, bj, aj)) g_keysA[i] = 0xFFFFFFFFu;
                    }
                }
                __syncthreads();
            }
            for (int j2 = tid; j2 < s_nsel; j2 += K4T) {
                int gw = s_fbidx[j2];
                int H, abase, local;
                const float* p = box_ptr(gw, g0, g1, g2, H, abase, local);
                float bestv = -3.4e38f; int bi = 0;
                for (int cc = 0; cc < 80; ++cc) {
                    float v = p[5 + cc];
                    if (v > bestv) { bestv = v; bi = cc; }
                }
                o_cls[j2] = bi;
            }
            __syncthreads();
        }
    }

    // ================= output =================
    int ns = s_nsel;
    for (int i = tid; i < out_size; i += K4T) {
        float v = 0.0f;
        if (i < 400) {
            int j = i >> 2;
            if (j < ns) v = ((float*)o_box)[i];
        } else if (i < 500) {
            int j = i - 400;
            if (j < ns) v = o_score[j];
        } else if (i < 600) {
            int j = i - 500;
            if (j < ns) v = (float)o_cls[j];
        } else if (i == 600) {
            v = (float)ns;
        }
        out[i] = v;
    }

    // ---- self-clean persistent state for next launch ----
    __syncthreads();
    if (tid == 0) {
        g_ticket = 0u;
        g_overflow = 0u;
        g_done = 0u;
    }
}

// ---------------- launch ----------------
extern "C" void kernel_launch(void* const* d_in, const int* in_sizes, int n_in,
                              void* d_out, int out_size) {
    const float* g0   = (const float*)d_in[0];
    const float* g1   = (const float*)d_in[1];
    const float* g2   = (const float*)d_in[2];
    const float* anch = (const float*)d_in[3];
    float* out = (float*)d_out;

    cudaFuncSetAttribute(k1_kernel, cudaFuncAttributeMaxDynamicSharedMemorySize, K1SM);
    cudaFuncSetAttribute(k4_kernel, cudaFuncAttributeMaxDynamicSharedMemorySize, K4SM);

    k1_kernel<<<K1NB, K1T, K1SM>>>(g0, g1, g2);
    k3_kernel<<<GBLK, 1024>>>(g0, g1, g2, anch);
    k4_kernel<<<1, K4T, K4SM>>>(g0, g1, g2, anch, out, out_size);
}